// round 9
// baseline (speedup 1.0000x reference)
#include <cuda_runtime.h>

#define T_LEN 1024
#define D_IN  1024
#define H_HID 512
#define G4    2048
#define BATCH 32
#define ROWS  32768          // T*B
#define NCOL  4096           // 2 dirs * 4H

// ---------------- device scratch ----------------
__device__ __align__(256) float g_xA[(size_t)D_IN * ROWS];   // x^T: [k][row]
__device__ __align__(256) float g_xg[(size_t)NCOL * ROWS];   // input proj, col-major
__device__ __align__(256) float g_hbuf[2][2][H_HID * BATCH]; // [buf][dir][k*32+b]
__device__ __align__(256) float g_part[128][T_LEN][BATCH];   // per-block logit partials
__device__ __align__(256) unsigned g_flag[2][64];            // per-block completed-step counters

// ---------------- f32x2 helpers ----------------
__device__ __forceinline__ unsigned long long splat2(float v) {
    unsigned long long r; unsigned u = __float_as_uint(v);
    asm("mov.b64 %0, {%1, %1};" : "=l"(r) : "r"(u));
    return r;
}
#define FMA2(acc, xv, wv) \
    asm("fma.rn.f32x2 %0, %1, %2, %0;" : "+l"(acc) : "l"(xv), "l"(wv))
__device__ __forceinline__ void unpack2(unsigned long long a, float& lo, float& hi) {
    unsigned l, h;
    asm("mov.b64 {%0, %1}, %2;" : "=r"(l), "=r"(h) : "l"(a));
    lo = __uint_as_float(l); hi = __uint_as_float(h);
}

// ---------------- acquire/release helpers ----------------
__device__ __forceinline__ unsigned ld_acq(const unsigned* p) {
    unsigned v;
    asm volatile("ld.global.acquire.gpu.u32 %0, [%1];" : "=r"(v) : "l"(p) : "memory");
    return v;
}
__device__ __forceinline__ void st_rel(unsigned* p, unsigned v) {
    asm volatile("st.global.release.gpu.u32 [%0], %1;" :: "l"(p), "r"(v) : "memory");
}

// ---------------- kernel 1: zero recurrent state + flags ----------------
__global__ void zero_state_kernel() {
    int i = blockIdx.x * blockDim.x + threadIdx.x;
    ((float*)g_hbuf)[i] = 0.0f;       // 65536 threads exactly
    if (i < 128) ((unsigned*)g_flag)[i] = 0u;
}

// ---------------- kernel 2: transpose x[B][T][D] -> xA[k][t*32+b] ----------------
__global__ void transpose_x_kernel(const float* __restrict__ x) {
    __shared__ float tile[32][33];
    int t = blockIdx.x, k0 = blockIdx.y * 32, tid = threadIdx.x;
    int kk = tid & 31, r = tid >> 5;
#pragma unroll
    for (int i = 0; i < 4; ++i) {
        int b = r + i * 8;
        tile[kk][b] = x[((size_t)b * T_LEN + t) * D_IN + k0 + kk];
    }
    __syncthreads();
    int b2 = tid & 31, kr = tid >> 5;
#pragma unroll
    for (int i = 0; i < 4; ++i) {
        int kk2 = kr + i * 8;
        g_xA[(size_t)(k0 + kk2) * ROWS + t * 32 + b2] = tile[kk2][b2];
    }
}

// ---------------- kernel 3: xg = A @ [Wx_f | Wx_b]  (fp32 FFMA2 GEMM) ----------------
__global__ void __launch_bounds__(256, 2)
gemm_kernel(const float* __restrict__ Wx_f, const float* __restrict__ Wx_b) {
    extern __shared__ float sm[];
    float* xs  = sm;          // [2][32*128]  A tile  [kk][row]
    float* ws2 = sm + 8192;   // [2][32*128]  W tile, duplicated pairs [kk][col*2]

    const int tid = threadIdx.x;
    const int cb = blockIdx.x, rb = blockIdx.y;
    const int r = tid & 15, cg = tid >> 4;

    unsigned long long acc[4][4];
#pragma unroll
    for (int p = 0; p < 4; ++p)
#pragma unroll
        for (int c = 0; c < 4; ++c) acc[p][c] = 0ull;

    float4 ar[4], wr[2];

    auto load_regs = [&](int ti) {
        int k0 = ti * 32;
#pragma unroll
        for (int i = 0; i < 4; ++i) {
            int f = tid + i * 256;
            int kk = f >> 5, rc = (f & 31) * 4;
            ar[i] = *(const float4*)(g_xA + (size_t)(k0 + kk) * ROWS + rb * 128 + rc);
        }
#pragma unroll
        for (int i = 0; i < 2; ++i) {
            int f = tid + i * 256;
            int kk = f >> 4, cc = (f & 15) * 4;
            int gcol = cb * 64 + cc;
            const float* src = (gcol < G4)
                ? (Wx_f + (size_t)(k0 + kk) * G4 + gcol)
                : (Wx_b + (size_t)(k0 + kk) * G4 + (gcol - G4));
            wr[i] = *(const float4*)src;
        }
    };
    auto store_smem = [&](int buf) {
        float* xb = xs + buf * 4096;
        float* wb = ws2 + buf * 4096;
#pragma unroll
        for (int i = 0; i < 4; ++i) {
            int f = tid + i * 256;
            int kk = f >> 5, rc = (f & 31) * 4;
            *(float4*)(xb + kk * 128 + rc) = ar[i];
        }
#pragma unroll
        for (int i = 0; i < 2; ++i) {
            int f = tid + i * 256;
            int kk = f >> 4, cc = (f & 15) * 4;
            float4 w = wr[i];
            *(float4*)(wb + kk * 128 + cc * 2)     = make_float4(w.x, w.x, w.y, w.y);
            *(float4*)(wb + kk * 128 + cc * 2 + 4) = make_float4(w.z, w.z, w.w, w.w);
        }
    };

    load_regs(0);
    store_smem(0);
    __syncthreads();

    for (int ti = 0; ti < 32; ++ti) {
        if (ti + 1 < 32) load_regs(ti + 1);
        const float* xb = xs + (ti & 1) * 4096 + r * 8;
        const float* wb = ws2 + (ti & 1) * 4096 + cg * 8;
#pragma unroll 4
        for (int kk = 0; kk < 32; ++kk) {
            ulonglong2 xq0 = *(const ulonglong2*)(xb);
            ulonglong2 xq1 = *(const ulonglong2*)(xb + 4);
            ulonglong2 wq0 = *(const ulonglong2*)(wb);
            ulonglong2 wq1 = *(const ulonglong2*)(wb + 4);
            FMA2(acc[0][0], xq0.x, wq0.x); FMA2(acc[0][1], xq0.x, wq0.y);
            FMA2(acc[0][2], xq0.x, wq1.x); FMA2(acc[0][3], xq0.x, wq1.y);
            FMA2(acc[1][0], xq0.y, wq0.x); FMA2(acc[1][1], xq0.y, wq0.y);
            FMA2(acc[1][2], xq0.y, wq1.x); FMA2(acc[1][3], xq0.y, wq1.y);
            FMA2(acc[2][0], xq1.x, wq0.x); FMA2(acc[2][1], xq1.x, wq0.y);
            FMA2(acc[2][2], xq1.x, wq1.x); FMA2(acc[2][3], xq1.x, wq1.y);
            FMA2(acc[3][0], xq1.y, wq0.x); FMA2(acc[3][1], xq1.y, wq0.y);
            FMA2(acc[3][2], xq1.y, wq1.x); FMA2(acc[3][3], xq1.y, wq1.y);
            xb += 128; wb += 128;
        }
        if (ti + 1 < 32) store_smem((ti + 1) & 1);
        __syncthreads();
    }

#pragma unroll
    for (int c = 0; c < 4; ++c) {
        float v[8];
#pragma unroll
        for (int p = 0; p < 4; ++p) unpack2(acc[p][c], v[2 * p], v[2 * p + 1]);
        size_t col = (size_t)cb * 64 + cg * 4 + c;
        float* d = g_xg + col * ROWS + rb * 128 + r * 8;
        *(float4*)d       = make_float4(v[0], v[1], v[2], v[3]);
        *(float4*)(d + 4) = make_float4(v[4], v[5], v[6], v[7]);
    }
}

// ---------------- kernel 4: persistent recurrent phase ----------------
// 128 blocks, 256 threads. dir = blk>>6, 8 hidden units/block (j0=(blk&63)*8)
// = 32 gate columns. 16-way k-split, thread tile = 8 batch x 8 cols.
// Decentralized sync: warp w consumes k in [64w, 64w+64) produced by blocks
// 8w..8w+7; it polls ONLY those 8 flags, copies its own 8KB h-chunk, and
// proceeds. No block-wide pre-k-loop barrier.
__global__ void __launch_bounds__(256, 1)
lstm_kernel(const float* __restrict__ Wh_f, const float* __restrict__ Wh_b,
            const float* __restrict__ b_f,  const float* __restrict__ b_b,
            const float* __restrict__ Wfc)
{
    extern __shared__ float sm[];
    float* hs   = sm;             // 16384 fl (64KB) : h(t-1) [k][b]
    float* ws   = sm + 16384;     // 16384 fl (64KB) : Wh slice [k][cc]
    float* part = sm + 32768;     // 16384 fl (64KB) : [slice][cc][b]
    float* psum = sm + 49152;     // 256 fl

    const int tid  = threadIdx.x;
    const int blk  = blockIdx.x;
    const int dir  = blk >> 6;
    const int j0   = (blk & 63) * 8;
    const int w    = tid >> 5;           // warp 0..7
    const int lane = tid & 31;

    // k-loop mapping: 16 slices x 16 threads; tile = 8 b x 8 cols
    const int slice = tid >> 4;          // 0..15 (k range slice*32..+31)
    const int q     = tid & 15;
    const int bo    = q >> 2;            // batch octet
    const int cq    = q & 3;             // col octet

    // cell mapping
    const int u = tid >> 5;              // hidden unit 0..7
    const int b = tid & 31;              // batch

    const float* Wh   = dir ? Wh_b : Wh_f;
    const float* bias = dir ? b_b  : b_f;

    // load Wh slice once: ws[k*32 + cc] = Wh[k][(cc>>3)*512 + j0 + (cc&7)]
    for (int e = tid; e < 512 * 32; e += 256) {
        int k = e >> 5, cc = e & 31;
        ws[e] = Wh[(size_t)k * G4 + (cc >> 3) * 512 + j0 + (cc & 7)];
    }

    float biasr[4];
#pragma unroll
    for (int g = 0; g < 4; ++g) biasr[g] = bias[g * 512 + j0 + u];
    const float wfc = Wfc[dir * H_HID + j0 + u];

    // this warp's producer flag (each of 8 flags read by 4 lanes, one 32B sector)
    const unsigned* myflag = &g_flag[dir][w * 8 + (lane & 7)];

    float cstate = 0.0f;
    __syncthreads();

    for (int s = 0; s < T_LEN; ++s) {
        const int t = dir ? (T_LEN - 1 - s) : s;
        const float* hprev = g_hbuf[s & 1][dir];
        float*       hnext = g_hbuf[(s + 1) & 1][dir];

        // prefetch xg (independent of h)
        float xgv[4];
#pragma unroll
        for (int g = 0; g < 4; ++g)
            xgv[g] = __ldg(g_xg + (size_t)(dir * G4 + g * 512 + j0 + u) * ROWS + t * 32 + b);

        // per-warp producer wait: 8 flags for k in [64w, 64w+64)
        if (s > 0) {
            bool ok;
            do { ok = ld_acq(myflag) >= (unsigned)s; }
            while (!__all_sync(0xffffffffu, ok));
        }
        __syncwarp();

        // per-warp h staging: 8KB chunk, 16 float4 per lane
        {
            const float4* src = (const float4*)(hprev + w * 64 * 32);
            float4* dst = (float4*)(hs + w * 64 * 32);
#pragma unroll
            for (int i = 0; i < 16; ++i) dst[lane + i * 32] = src[lane + i * 32];
        }
        __syncwarp();

        // k-loop: 32 k's; per k: 2 LDS.128 h + 2 LDS.128 w + 8 splat + 32 FMA2
        unsigned long long acc[8][4];
#pragma unroll
        for (int bi = 0; bi < 8; ++bi)
#pragma unroll
            for (int cp = 0; cp < 4; ++cp) acc[bi][cp] = 0ull;
        {
            const float* hp = hs + slice * 32 * 32 + bo * 8;
            const float* wp = ws + slice * 32 * 32 + cq * 8;
#pragma unroll 2
            for (int kk = 0; kk < 32; ++kk) {
                float4 h0 = *(const float4*)hp;
                float4 h1 = *(const float4*)(hp + 4);
                ulonglong2 wq0 = *(const ulonglong2*)wp;
                ulonglong2 wq1 = *(const ulonglong2*)(wp + 4);
                unsigned long long s0 = splat2(h0.x), s1 = splat2(h0.y);
                unsigned long long s2 = splat2(h0.z), s3 = splat2(h0.w);
                unsigned long long s4 = splat2(h1.x), s5 = splat2(h1.y);
                unsigned long long s6 = splat2(h1.z), s7 = splat2(h1.w);
                FMA2(acc[0][0], s0, wq0.x); FMA2(acc[0][1], s0, wq0.y);
                FMA2(acc[0][2], s0, wq1.x); FMA2(acc[0][3], s0, wq1.y);
                FMA2(acc[1][0], s1, wq0.x); FMA2(acc[1][1], s1, wq0.y);
                FMA2(acc[1][2], s1, wq1.x); FMA2(acc[1][3], s1, wq1.y);
                FMA2(acc[2][0], s2, wq0.x); FMA2(acc[2][1], s2, wq0.y);
                FMA2(acc[2][2], s2, wq1.x); FMA2(acc[2][3], s2, wq1.y);
                FMA2(acc[3][0], s3, wq0.x); FMA2(acc[3][1], s3, wq0.y);
                FMA2(acc[3][2], s3, wq1.x); FMA2(acc[3][3], s3, wq1.y);
                FMA2(acc[4][0], s4, wq0.x); FMA2(acc[4][1], s4, wq0.y);
                FMA2(acc[4][2], s4, wq1.x); FMA2(acc[4][3], s4, wq1.y);
                FMA2(acc[5][0], s5, wq0.x); FMA2(acc[5][1], s5, wq0.y);
                FMA2(acc[5][2], s5, wq1.x); FMA2(acc[5][3], s5, wq1.y);
                FMA2(acc[6][0], s6, wq0.x); FMA2(acc[6][1], s6, wq0.y);
                FMA2(acc[6][2], s6, wq1.x); FMA2(acc[6][3], s6, wq1.y);
                FMA2(acc[7][0], s7, wq0.x); FMA2(acc[7][1], s7, wq0.y);
                FMA2(acc[7][2], s7, wq1.x); FMA2(acc[7][3], s7, wq1.y);
                hp += 32; wp += 32;
            }
        }
        // write k-split partials: part[slice][cc][b]
        {
            float* pb = part + slice * 1024 + bo * 8;
#pragma unroll
            for (int cp = 0; cp < 4; ++cp) {
                float* p0 = pb + (cq * 8 + 2 * cp) * 32;
#pragma unroll
                for (int bi = 0; bi < 8; ++bi) {
                    float lo, hi;
                    unpack2(acc[bi][cp], lo, hi);
                    p0[bi]      = lo;
                    p0[32 + bi] = hi;
                }
            }
        }
        __syncthreads();

        // epilogue: thread (u, b) computes cell update
        {
            float gate[4];
#pragma unroll
            for (int g = 0; g < 4; ++g) {
                float sum = xgv[g] + biasr[g];
                const float* pp = part + (g * 8 + u) * 32 + b;
#pragma unroll
                for (int sl = 0; sl < 16; ++sl) sum += pp[sl * 1024];
                gate[g] = sum;
            }
            float iv = 1.0f / (1.0f + __expf(-gate[0]));
            float fv = 1.0f / (1.0f + __expf(-gate[1]));
            float gv = tanhf(gate[2]);
            float ov = 1.0f / (1.0f + __expf(-gate[3]));
            cstate = fv * cstate + iv * gv;
            float hv = ov * tanhf(cstate);
            hnext[(j0 + u) * 32 + b] = hv;
            psum[tid] = hv * wfc;
        }
        __syncthreads();
        // publish step completion (h writes ordered by syncthreads before release)
        if (tid == 64 && s + 1 < T_LEN)
            st_rel(&g_flag[dir][blk & 63], (unsigned)(s + 1));
        if (tid < 32) {
            float tot = 0.0f;
#pragma unroll
            for (int uu = 0; uu < 8; ++uu) tot += psum[tid + uu * 32];
            g_part[blk][t][tid] = tot;
        }
    }
}

// ---------------- kernel 5: reduce partials + sigmoid ----------------
__global__ void finalize_kernel(const float* __restrict__ b_fc, float* __restrict__ out) {
    int g = blockIdx.x * blockDim.x + threadIdx.x;
    if (g >= T_LEN * BATCH) return;
    int t = g >> 5, b = g & 31;
    float acc = b_fc[0];
    const float* p = &g_part[0][t][b];
#pragma unroll 8
    for (int blk = 0; blk < 128; ++blk)
        acc += p[(size_t)blk * T_LEN * BATCH];
    out[(size_t)b * T_LEN + t] = 1.0f / (1.0f + __expf(-acc));
}

// ---------------- launcher ----------------
extern "C" void kernel_launch(void* const* d_in, const int* in_sizes, int n_in,
                              void* d_out, int out_size) {
    const float* x    = (const float*)d_in[0];
    const float* Wx_f = (const float*)d_in[1];
    const float* Wh_f = (const float*)d_in[2];
    const float* b_f  = (const float*)d_in[3];
    const float* Wx_b = (const float*)d_in[4];
    const float* Wh_b = (const float*)d_in[5];
    const float* b_b  = (const float*)d_in[6];
    const float* Wfc  = (const float*)d_in[7];
    const float* bfc  = (const float*)d_in[8];
    float* out = (float*)d_out;
    (void)in_sizes; (void)n_in; (void)out_size;

    cudaFuncSetAttribute(gemm_kernel, cudaFuncAttributeMaxDynamicSharedMemorySize, 65536);
    cudaFuncSetAttribute(lstm_kernel, cudaFuncAttributeMaxDynamicSharedMemorySize, 197632);

    zero_state_kernel<<<256, 256>>>();
    transpose_x_kernel<<<dim3(T_LEN, D_IN / 32), 256>>>(x);
    gemm_kernel<<<dim3(64, 256), 256, 65536>>>(Wx_f, Wx_b);
    lstm_kernel<<<128, 256, 197632>>>(Wh_f, Wh_b, b_f, b_b, Wfc);
    finalize_kernel<<<128, 256>>>(bfc, out);
}

// round 10
// speedup vs baseline: 1.2525x; 1.2525x over previous
#include <cuda_runtime.h>

#define T_LEN 1024
#define D_IN  1024
#define H_HID 512
#define G4    2048
#define BATCH 32
#define ROWS  32768          // T*B
#define NCOL  4096           // 2 dirs * 4H

// ---------------- device scratch ----------------
__device__ __align__(256) float g_xA[(size_t)D_IN * ROWS];   // x^T: [k][row]
__device__ __align__(256) float g_xg[(size_t)NCOL * ROWS];   // input proj, col-major
__device__ __align__(256) float g_hbuf[2][2][H_HID * BATCH]; // [buf][dir][k*32+b]
__device__ __align__(256) float g_part[128][T_LEN][BATCH];   // per-block logit partials
__device__ __align__(256) unsigned g_flag[2][64];            // per-block completed-step counters
__device__ unsigned g_gen2[2];                               // per-dir published generation

// ---------------- f32x2 helpers ----------------
__device__ __forceinline__ unsigned long long splat2(float v) {
    unsigned long long r; unsigned u = __float_as_uint(v);
    asm("mov.b64 %0, {%1, %1};" : "=l"(r) : "r"(u));
    return r;
}
#define FMA2(acc, xv, wv) \
    asm("fma.rn.f32x2 %0, %1, %2, %0;" : "+l"(acc) : "l"(xv), "l"(wv))
#define ADD2(acc, v) \
    asm("add.rn.f32x2 %0, %0, %1;" : "+l"(acc) : "l"(v))
__device__ __forceinline__ void unpack2(unsigned long long a, float& lo, float& hi) {
    unsigned l, h;
    asm("mov.b64 {%0, %1}, %2;" : "=r"(l), "=r"(h) : "l"(a));
    lo = __uint_as_float(l); hi = __uint_as_float(h);
}

// ---------------- acquire/release + mbarrier + bulk-copy helpers ----------------
__device__ __forceinline__ unsigned ld_acq(const unsigned* p) {
    unsigned v;
    asm volatile("ld.global.acquire.gpu.u32 %0, [%1];" : "=r"(v) : "l"(p) : "memory");
    return v;
}
__device__ __forceinline__ void st_rel(unsigned* p, unsigned v) {
    asm volatile("st.global.release.gpu.u32 [%0], %1;" :: "l"(p), "r"(v) : "memory");
}
__device__ __forceinline__ unsigned smem_u32(const void* p) {
    unsigned a;
    asm("{ .reg .u64 t; cvta.to.shared.u64 t, %1; cvt.u32.u64 %0, t; }" : "=r"(a) : "l"(p));
    return a;
}
__device__ __forceinline__ void mbar_init(unsigned mbar, unsigned count) {
    asm volatile("mbarrier.init.shared.b64 [%0], %1;" :: "r"(mbar), "r"(count) : "memory");
}
__device__ __forceinline__ void mbar_expect_tx(unsigned mbar, unsigned bytes) {
    asm volatile("mbarrier.arrive.expect_tx.shared.b64 _, [%0], %1;"
                 :: "r"(mbar), "r"(bytes) : "memory");
}
__device__ __forceinline__ void bulk_g2s(unsigned dst_smem, const void* src, unsigned bytes,
                                         unsigned mbar) {
    asm volatile(
        "cp.async.bulk.shared::cta.global.mbarrier::complete_tx::bytes [%0], [%1], %2, [%3];"
        :: "r"(dst_smem), "l"(src), "r"(bytes), "r"(mbar) : "memory");
}
__device__ __forceinline__ void mbar_wait(unsigned mbar, unsigned parity) {
    asm volatile(
        "{\n\t.reg .pred P;\n"
        "W%=:\n\t"
        "mbarrier.try_wait.parity.acquire.cta.shared::cta.b64 P, [%0], %1, 0x989680;\n\t"
        "@P bra D%=;\n\t"
        "bra W%=;\n"
        "D%=:\n\t}"
        :: "r"(mbar), "r"(parity) : "memory");
}

// ---------------- kernel 1: zero recurrent state + flags ----------------
__global__ void zero_state_kernel() {
    int i = blockIdx.x * blockDim.x + threadIdx.x;
    ((float*)g_hbuf)[i] = 0.0f;       // 65536 threads exactly
    if (i < 128) ((unsigned*)g_flag)[i] = 0u;
    if (i < 2)   g_gen2[i] = 0u;
}

// ---------------- kernel 2: transpose x[B][T][D] -> xA[k][t*32+b] ----------------
__global__ void transpose_x_kernel(const float* __restrict__ x) {
    __shared__ float tile[32][33];
    int t = blockIdx.x, k0 = blockIdx.y * 32, tid = threadIdx.x;
    int kk = tid & 31, r = tid >> 5;
#pragma unroll
    for (int i = 0; i < 4; ++i) {
        int b = r + i * 8;
        tile[kk][b] = x[((size_t)b * T_LEN + t) * D_IN + k0 + kk];
    }
    __syncthreads();
    int b2 = tid & 31, kr = tid >> 5;
#pragma unroll
    for (int i = 0; i < 4; ++i) {
        int kk2 = kr + i * 8;
        g_xA[(size_t)(k0 + kk2) * ROWS + t * 32 + b2] = tile[kk2][b2];
    }
}

// ---------------- kernel 3: xg = A @ [Wx_f | Wx_b]  (fp32 FFMA2 GEMM) ----------------
__global__ void __launch_bounds__(256, 2)
gemm_kernel(const float* __restrict__ Wx_f, const float* __restrict__ Wx_b) {
    extern __shared__ float sm[];
    float* xs  = sm;          // [2][32*128]  A tile  [kk][row]
    float* ws2 = sm + 8192;   // [2][32*128]  W tile, duplicated pairs [kk][col*2]

    const int tid = threadIdx.x;
    const int cb = blockIdx.x, rb = blockIdx.y;
    const int r = tid & 15, cg = tid >> 4;

    unsigned long long acc[4][4];
#pragma unroll
    for (int p = 0; p < 4; ++p)
#pragma unroll
        for (int c = 0; c < 4; ++c) acc[p][c] = 0ull;

    float4 ar[4], wr[2];

    auto load_regs = [&](int ti) {
        int k0 = ti * 32;
#pragma unroll
        for (int i = 0; i < 4; ++i) {
            int f = tid + i * 256;
            int kk = f >> 5, rc = (f & 31) * 4;
            ar[i] = *(const float4*)(g_xA + (size_t)(k0 + kk) * ROWS + rb * 128 + rc);
        }
#pragma unroll
        for (int i = 0; i < 2; ++i) {
            int f = tid + i * 256;
            int kk = f >> 4, cc = (f & 15) * 4;
            int gcol = cb * 64 + cc;
            const float* src = (gcol < G4)
                ? (Wx_f + (size_t)(k0 + kk) * G4 + gcol)
                : (Wx_b + (size_t)(k0 + kk) * G4 + (gcol - G4));
            wr[i] = *(const float4*)src;
        }
    };
    auto store_smem = [&](int buf) {
        float* xb = xs + buf * 4096;
        float* wb = ws2 + buf * 4096;
#pragma unroll
        for (int i = 0; i < 4; ++i) {
            int f = tid + i * 256;
            int kk = f >> 5, rc = (f & 31) * 4;
            *(float4*)(xb + kk * 128 + rc) = ar[i];
        }
#pragma unroll
        for (int i = 0; i < 2; ++i) {
            int f = tid + i * 256;
            int kk = f >> 4, cc = (f & 15) * 4;
            float4 w = wr[i];
            *(float4*)(wb + kk * 128 + cc * 2)     = make_float4(w.x, w.x, w.y, w.y);
            *(float4*)(wb + kk * 128 + cc * 2 + 4) = make_float4(w.z, w.z, w.w, w.w);
        }
    };

    load_regs(0);
    store_smem(0);
    __syncthreads();

    for (int ti = 0; ti < 32; ++ti) {
        if (ti + 1 < 32) load_regs(ti + 1);
        const float* xb = xs + (ti & 1) * 4096 + r * 8;
        const float* wb = ws2 + (ti & 1) * 4096 + cg * 8;
#pragma unroll 4
        for (int kk = 0; kk < 32; ++kk) {
            ulonglong2 xq0 = *(const ulonglong2*)(xb);
            ulonglong2 xq1 = *(const ulonglong2*)(xb + 4);
            ulonglong2 wq0 = *(const ulonglong2*)(wb);
            ulonglong2 wq1 = *(const ulonglong2*)(wb + 4);
            FMA2(acc[0][0], xq0.x, wq0.x); FMA2(acc[0][1], xq0.x, wq0.y);
            FMA2(acc[0][2], xq0.x, wq1.x); FMA2(acc[0][3], xq0.x, wq1.y);
            FMA2(acc[1][0], xq0.y, wq0.x); FMA2(acc[1][1], xq0.y, wq0.y);
            FMA2(acc[1][2], xq0.y, wq1.x); FMA2(acc[1][3], xq0.y, wq1.y);
            FMA2(acc[2][0], xq1.x, wq0.x); FMA2(acc[2][1], xq1.x, wq0.y);
            FMA2(acc[2][2], xq1.x, wq1.x); FMA2(acc[2][3], xq1.x, wq1.y);
            FMA2(acc[3][0], xq1.y, wq0.x); FMA2(acc[3][1], xq1.y, wq0.y);
            FMA2(acc[3][2], xq1.y, wq1.x); FMA2(acc[3][3], xq1.y, wq1.y);
            xb += 128; wb += 128;
        }
        if (ti + 1 < 32) store_smem((ti + 1) & 1);
        __syncthreads();
    }

#pragma unroll
    for (int c = 0; c < 4; ++c) {
        float v[8];
#pragma unroll
        for (int p = 0; p < 4; ++p) unpack2(acc[p][c], v[2 * p], v[2 * p + 1]);
        size_t col = (size_t)cb * 64 + cg * 4 + c;
        float* d = g_xg + col * ROWS + rb * 128 + r * 8;
        *(float4*)d       = make_float4(v[0], v[1], v[2], v[3]);
        *(float4*)(d + 4) = make_float4(v[4], v[5], v[6], v[7]);
    }
}

// ---------------- kernel 4: persistent recurrent phase ----------------
// 128 blocks, 512 threads (4 warps/SMSP). dir = blk>>6, 8 hidden units/block.
// 32 k-slices of 16 k, thread tile 8b x 8c (32 FMA2/k). Warp's two half-warp
// slices shuffle-combined before smem partial write (partials stay 64KB).
// Barrier: R8 checker->gen (tid0-only polling). h staged via cp.async.bulk.
__global__ void __launch_bounds__(512, 1)
lstm_kernel(const float* __restrict__ Wh_f, const float* __restrict__ Wh_b,
            const float* __restrict__ b_f,  const float* __restrict__ b_b,
            const float* __restrict__ Wfc)
{
    extern __shared__ float sm[];
    float* hs   = sm;             // 16384 fl (64KB) : h(t-1) [k][b]
    float* ws   = sm + 16384;     // 16384 fl (64KB) : Wh slice [k][cc]
    float* part = sm + 32768;     // 16384 fl (64KB) : [pair][cc][b]
    float* psum = sm + 49152;     // 256 fl
    unsigned long long* mbar_p = (unsigned long long*)(sm + 49408);

    const int tid  = threadIdx.x;
    const int blk  = blockIdx.x;
    const int dir  = blk >> 6;
    const int j0   = (blk & 63) * 8;
    const bool checker = ((blk & 63) == 0);
    const int w    = tid >> 5;           // warp 0..15 (= slice pair id)
    const int lane = tid & 31;

    // k-loop mapping: 32 slices x 16 threads; slice covers 16 k's
    const int slice = tid >> 4;          // 0..31
    const int q     = tid & 15;
    const int bo    = q >> 2;            // batch octet
    const int cq    = q & 3;             // col octet

    // cell mapping (tid < 256)
    const int u = tid >> 5;              // 0..7 for tid<256
    const int b = tid & 31;

    const float* Wh   = dir ? Wh_b : Wh_f;
    const float* bias = dir ? b_b  : b_f;

    const unsigned mbar = smem_u32(mbar_p);
    const unsigned hs_u = smem_u32(hs);
    if (tid == 0) mbar_init(mbar, 1);

    // load Wh slice once: ws[k*32 + cc] = Wh[k][(cc>>3)*512 + j0 + (cc&7)]
    for (int e = tid; e < 512 * 32; e += 512) {
        int k = e >> 5, cc = e & 31;
        ws[e] = Wh[(size_t)k * G4 + (cc >> 3) * 512 + j0 + (cc & 7)];
    }

    float biasr[4] = {0, 0, 0, 0};
    float wfc = 0.0f;
    if (tid < 256) {
#pragma unroll
        for (int g = 0; g < 4; ++g) biasr[g] = bias[g * 512 + j0 + u];
        wfc = Wfc[dir * H_HID + j0 + u];
    }

    float cstate = 0.0f;
    __syncthreads();

    for (int s = 0; s < T_LEN; ++s) {
        const int t = dir ? (T_LEN - 1 - s) : s;
        const float* hprev = g_hbuf[s & 1][dir];
        float*       hnext = g_hbuf[(s + 1) & 1][dir];

        // prefetch xg (independent of h)
        float xgv[4] = {0, 0, 0, 0};
        if (tid < 256) {
#pragma unroll
            for (int g = 0; g < 4; ++g)
                xgv[g] = __ldg(g_xg + (size_t)(dir * G4 + g * 512 + j0 + u) * ROWS + t * 32 + b);
        }

        // inter-block sync: flags -> checker -> gen  (tid0-only polling)
        if (s > 0) {
            if (checker) {
                if (tid < 32) {
                    const unsigned* fa = &g_flag[dir][tid];
                    const unsigned* fb = &g_flag[dir][tid + 32];
                    bool ok;
                    do {
                        ok = (ld_acq(fa) >= (unsigned)s) && (ld_acq(fb) >= (unsigned)s);
                    } while (!__all_sync(0xffffffffu, ok));
                    if (tid == 0) st_rel(&g_gen2[dir], (unsigned)s);
                }
            } else {
                if (tid == 0) {
                    while (ld_acq(&g_gen2[dir]) < (unsigned)s) { }
                }
            }
        }
        // async stage h(t-1): 64KB in one bulk copy
        if (tid == 0) {
            mbar_expect_tx(mbar, 65536u);
            bulk_g2s(hs_u, hprev, 65536u, mbar);
        }
        mbar_wait(mbar, s & 1);

        // k-loop: 16 k's; per k: 2 LDS.128 h + 2 LDS.128 w + 8 splat + 32 FMA2
        unsigned long long acc[8][4];
#pragma unroll
        for (int bi = 0; bi < 8; ++bi)
#pragma unroll
            for (int cp = 0; cp < 4; ++cp) acc[bi][cp] = 0ull;
        {
            const float* hp = hs + slice * 16 * 32 + bo * 8;
            const float* wp = ws + slice * 16 * 32 + cq * 8;
#pragma unroll 2
            for (int kk = 0; kk < 16; ++kk) {
                float4 h0 = *(const float4*)hp;
                float4 h1 = *(const float4*)(hp + 4);
                ulonglong2 wq0 = *(const ulonglong2*)wp;
                ulonglong2 wq1 = *(const ulonglong2*)(wp + 4);
                unsigned long long s0 = splat2(h0.x), s1 = splat2(h0.y);
                unsigned long long s2 = splat2(h0.z), s3 = splat2(h0.w);
                unsigned long long s4 = splat2(h1.x), s5 = splat2(h1.y);
                unsigned long long s6 = splat2(h1.z), s7 = splat2(h1.w);
                FMA2(acc[0][0], s0, wq0.x); FMA2(acc[0][1], s0, wq0.y);
                FMA2(acc[0][2], s0, wq1.x); FMA2(acc[0][3], s0, wq1.y);
                FMA2(acc[1][0], s1, wq0.x); FMA2(acc[1][1], s1, wq0.y);
                FMA2(acc[1][2], s1, wq1.x); FMA2(acc[1][3], s1, wq1.y);
                FMA2(acc[2][0], s2, wq0.x); FMA2(acc[2][1], s2, wq0.y);
                FMA2(acc[2][2], s2, wq1.x); FMA2(acc[2][3], s2, wq1.y);
                FMA2(acc[3][0], s3, wq0.x); FMA2(acc[3][1], s3, wq0.y);
                FMA2(acc[3][2], s3, wq1.x); FMA2(acc[3][3], s3, wq1.y);
                FMA2(acc[4][0], s4, wq0.x); FMA2(acc[4][1], s4, wq0.y);
                FMA2(acc[4][2], s4, wq1.x); FMA2(acc[4][3], s4, wq1.y);
                FMA2(acc[5][0], s5, wq0.x); FMA2(acc[5][1], s5, wq0.y);
                FMA2(acc[5][2], s5, wq1.x); FMA2(acc[5][3], s5, wq1.y);
                FMA2(acc[6][0], s6, wq0.x); FMA2(acc[6][1], s6, wq0.y);
                FMA2(acc[6][2], s6, wq1.x); FMA2(acc[6][3], s6, wq1.y);
                FMA2(acc[7][0], s7, wq0.x); FMA2(acc[7][1], s7, wq0.y);
                FMA2(acc[7][2], s7, wq1.x); FMA2(acc[7][3], s7, wq1.y);
                hp += 32; wp += 32;
            }
        }
        // combine the warp's two half-warp slices: lane L += lane L+16
#pragma unroll
        for (int bi = 0; bi < 8; ++bi)
#pragma unroll
            for (int cp = 0; cp < 4; ++cp) {
                unsigned long long o =
                    __shfl_down_sync(0xffffffffu, acc[bi][cp], 16);
                ADD2(acc[bi][cp], o);
            }
        // write combined partials: part[w][cc][b]  (lanes 0-15 only)
        if (lane < 16) {
            float* pb = part + w * 1024 + bo * 8;
#pragma unroll
            for (int cp = 0; cp < 4; ++cp) {
                float* p0 = pb + (cq * 8 + 2 * cp) * 32;
#pragma unroll
                for (int bi = 0; bi < 8; ++bi) {
                    float lo, hi;
                    unpack2(acc[bi][cp], lo, hi);
                    p0[bi]      = lo;
                    p0[32 + bi] = hi;
                }
            }
        }
        __syncthreads();

        // epilogue: thread (u, b) computes cell update (tid < 256)
        if (tid < 256) {
            float gate[4];
#pragma unroll
            for (int g = 0; g < 4; ++g) {
                float sum = xgv[g] + biasr[g];
                const float* pp = part + (g * 8 + u) * 32 + b;
#pragma unroll
                for (int sl = 0; sl < 16; ++sl) sum += pp[sl * 1024];
                gate[g] = sum;
            }
            float iv = 1.0f / (1.0f + __expf(-gate[0]));
            float fv = 1.0f / (1.0f + __expf(-gate[1]));
            float gv = tanhf(gate[2]);
            float ov = 1.0f / (1.0f + __expf(-gate[3]));
            cstate = fv * cstate + iv * gv;
            float hv = ov * tanhf(cstate);
            hnext[(j0 + u) * 32 + b] = hv;
            psum[tid] = hv * wfc;
        }
        __syncthreads();
        // publish step completion (hnext writes ordered by syncthreads)
        if (tid == 64 && s + 1 < T_LEN)
            st_rel(&g_flag[dir][blk & 63], (unsigned)(s + 1));
        if (tid < 32) {
            float tot = 0.0f;
#pragma unroll
            for (int uu = 0; uu < 8; ++uu) tot += psum[tid + uu * 32];
            g_part[blk][t][tid] = tot;
        }
    }
}

// ---------------- kernel 5: reduce partials + sigmoid ----------------
__global__ void finalize_kernel(const float* __restrict__ b_fc, float* __restrict__ out) {
    int g = blockIdx.x * blockDim.x + threadIdx.x;
    if (g >= T_LEN * BATCH) return;
    int t = g >> 5, b = g & 31;
    float acc = b_fc[0];
    const float* p = &g_part[0][t][b];
#pragma unroll 8
    for (int blk = 0; blk < 128; ++blk)
        acc += p[(size_t)blk * T_LEN * BATCH];
    out[(size_t)b * T_LEN + t] = 1.0f / (1.0f + __expf(-acc));
}

// ---------------- launcher ----------------
extern "C" void kernel_launch(void* const* d_in, const int* in_sizes, int n_in,
                              void* d_out, int out_size) {
    const float* x    = (const float*)d_in[0];
    const float* Wx_f = (const float*)d_in[1];
    const float* Wh_f = (const float*)d_in[2];
    const float* b_f  = (const float*)d_in[3];
    const float* Wx_b = (const float*)d_in[4];
    const float* Wh_b = (const float*)d_in[5];
    const float* b_b  = (const float*)d_in[6];
    const float* Wfc  = (const float*)d_in[7];
    const float* bfc  = (const float*)d_in[8];
    float* out = (float*)d_out;
    (void)in_sizes; (void)n_in; (void)out_size;

    cudaFuncSetAttribute(gemm_kernel, cudaFuncAttributeMaxDynamicSharedMemorySize, 65536);
    cudaFuncSetAttribute(lstm_kernel, cudaFuncAttributeMaxDynamicSharedMemorySize, 197664);

    zero_state_kernel<<<256, 256>>>();
    transpose_x_kernel<<<dim3(T_LEN, D_IN / 32), 256>>>(x);
    gemm_kernel<<<dim3(64, 256), 256, 65536>>>(Wx_f, Wx_b);
    lstm_kernel<<<128, 512, 197664>>>(Wh_f, Wh_b, b_f, b_b, Wfc);
    finalize_kernel<<<128, 256>>>(bfc, out);
}

// round 12
// speedup vs baseline: 2.3421x; 1.8699x over previous
#include <cuda_runtime.h>
#include <cuda_bf16.h>

#define T_LEN 1024
#define D_IN  1024
#define H_HID 512
#define G4    2048
#define BATCH 32
#define ROWS  32768          // T*B
#define NCOL  4096           // 2 dirs * 4H

// ---------------- device scratch ----------------
__device__ __align__(256) __nv_bfloat16 g_ahi[(size_t)ROWS * D_IN];  // A hi [row][k]
__device__ __align__(256) __nv_bfloat16 g_alo[(size_t)ROWS * D_IN];  // A lo
__device__ __align__(256) __nv_bfloat16 g_whi[(size_t)NCOL * D_IN];  // W^T hi [col][k]
__device__ __align__(256) __nv_bfloat16 g_wlo[(size_t)NCOL * D_IN];  // W^T lo
__device__ __align__(256) float g_xg[(size_t)NCOL * ROWS];   // input proj, col-major [col][row]
__device__ __align__(256) float g_hbuf[2][2][H_HID * BATCH]; // [buf][dir][k*32+b]
__device__ __align__(256) float g_part[128][T_LEN][BATCH];   // per-block logit partials
__device__ __align__(256) unsigned g_flag[2][64];            // per-block completed-step counters
__device__ unsigned g_gen2[2];                               // per-dir published generation

// ---------------- f32x2 helpers ----------------
__device__ __forceinline__ unsigned long long splat2(float v) {
    unsigned long long r; unsigned u = __float_as_uint(v);
    asm("mov.b64 %0, {%1, %1};" : "=l"(r) : "r"(u));
    return r;
}
#define FMA2(acc, xv, wv) \
    asm("fma.rn.f32x2 %0, %1, %2, %0;" : "+l"(acc) : "l"(xv), "l"(wv))
__device__ __forceinline__ void unpack2(unsigned long long a, float& lo, float& hi) {
    unsigned l, h;
    asm("mov.b64 {%0, %1}, %2;" : "=r"(l), "=r"(h) : "l"(a));
    lo = __uint_as_float(l); hi = __uint_as_float(h);
}

// ---------------- acquire/release + mbarrier + bulk-copy helpers ----------------
__device__ __forceinline__ unsigned ld_acq(const unsigned* p) {
    unsigned v;
    asm volatile("ld.global.acquire.gpu.u32 %0, [%1];" : "=r"(v) : "l"(p) : "memory");
    return v;
}
__device__ __forceinline__ void st_rel(unsigned* p, unsigned v) {
    asm volatile("st.global.release.gpu.u32 [%0], %1;" :: "l"(p), "r"(v) : "memory");
}
__device__ __forceinline__ unsigned smem_u32(const void* p) {
    unsigned a;
    asm("{ .reg .u64 t; cvta.to.shared.u64 t, %1; cvt.u32.u64 %0, t; }" : "=r"(a) : "l"(p));
    return a;
}
__device__ __forceinline__ void mbar_init(unsigned mbar, unsigned count) {
    asm volatile("mbarrier.init.shared.b64 [%0], %1;" :: "r"(mbar), "r"(count) : "memory");
}
__device__ __forceinline__ void mbar_expect_tx(unsigned mbar, unsigned bytes) {
    asm volatile("mbarrier.arrive.expect_tx.shared.b64 _, [%0], %1;"
                 :: "r"(mbar), "r"(bytes) : "memory");
}
__device__ __forceinline__ void bulk_g2s(unsigned dst_smem, const void* src, unsigned bytes,
                                         unsigned mbar) {
    asm volatile(
        "cp.async.bulk.shared::cta.global.mbarrier::complete_tx::bytes [%0], [%1], %2, [%3];"
        :: "r"(dst_smem), "l"(src), "r"(bytes), "r"(mbar) : "memory");
}
__device__ __forceinline__ void mbar_wait(unsigned mbar, unsigned parity) {
    asm volatile(
        "{\n\t.reg .pred P;\n"
        "W%=:\n\t"
        "mbarrier.try_wait.parity.acquire.cta.shared::cta.b64 P, [%0], %1, 0x989680;\n\t"
        "@P bra D%=;\n\t"
        "bra W%=;\n"
        "D%=:\n\t}"
        :: "r"(mbar), "r"(parity) : "memory");
}

// ---------------- mma / ldmatrix / cp.async helpers (sm_80-era, sm_103-safe) ----------
__device__ __forceinline__ void ldsm_x4(unsigned& r0, unsigned& r1, unsigned& r2, unsigned& r3,
                                        unsigned addr) {
    asm volatile("ldmatrix.sync.aligned.m8n8.x4.shared.b16 {%0,%1,%2,%3}, [%4];"
                 : "=r"(r0), "=r"(r1), "=r"(r2), "=r"(r3) : "r"(addr));
}
__device__ __forceinline__ void mma_bf16(float* d, unsigned a0, unsigned a1, unsigned a2,
                                         unsigned a3, unsigned b0, unsigned b1) {
    asm volatile(
        "mma.sync.aligned.m16n8k16.row.col.f32.bf16.bf16.f32 "
        "{%0,%1,%2,%3}, {%4,%5,%6,%7}, {%8,%9}, {%0,%1,%2,%3};"
        : "+f"(d[0]), "+f"(d[1]), "+f"(d[2]), "+f"(d[3])
        : "r"(a0), "r"(a1), "r"(a2), "r"(a3), "r"(b0), "r"(b1));
}
__device__ __forceinline__ void cp16(unsigned dst, const void* src) {
    asm volatile("cp.async.cg.shared.global [%0], [%1], 16;" :: "r"(dst), "l"(src));
}
__device__ __forceinline__ void cp_commit() { asm volatile("cp.async.commit_group;"); }
template <int N>
__device__ __forceinline__ void cp_wait() { asm volatile("cp.async.wait_group %0;" :: "n"(N)); }

#define SWZ(off) ((off) ^ (((off) >> 3) & 0x70))

// ---------------- kernel 1: zero recurrent state + flags ----------------
__global__ void zero_state_kernel() {
    int i = blockIdx.x * blockDim.x + threadIdx.x;
    ((float*)g_hbuf)[i] = 0.0f;       // 65536 threads exactly
    if (i < 128) ((unsigned*)g_flag)[i] = 0u;
    if (i < 2)   g_gen2[i] = 0u;
}

// ---------------- kernel 2a: x -> bf16 hi/lo, row = t*32+b, k-major ----------------
__global__ void conv_x_kernel(const float* __restrict__ x) {
    int idx = blockIdx.x * blockDim.x + threadIdx.x;
    int row = idx >> 7;
    int kc  = (idx & 127) * 8;
    int b = row & 31, t = row >> 5;
    const float4* src = (const float4*)(x + ((size_t)b * T_LEN + t) * D_IN + kc);
    float4 v0 = src[0], v1 = src[1];
    float vs[8] = {v0.x, v0.y, v0.z, v0.w, v1.x, v1.y, v1.z, v1.w};
    __nv_bfloat16 hi[8], lo[8];
#pragma unroll
    for (int i = 0; i < 8; ++i) {
        hi[i] = __float2bfloat16_rn(vs[i]);
        lo[i] = __float2bfloat16_rn(vs[i] - __bfloat162float(hi[i]));
    }
    *(uint4*)(g_ahi + (size_t)row * D_IN + kc) = *(uint4*)hi;
    *(uint4*)(g_alo + (size_t)row * D_IN + kc) = *(uint4*)lo;
}

// ---------------- kernel 2b: W [k][col] -> W^T bf16 hi/lo [col][k] ----------------
__global__ void conv_w_kernel(const float* __restrict__ Wx_f, const float* __restrict__ Wx_b) {
    __shared__ float tile[32][33];
    int cblk = blockIdx.x * 32;
    int kblk = blockIdx.y * 32;
    int tid = threadIdx.x;
    int cl = tid & 31, kr = tid >> 5;
#pragma unroll
    for (int i = 0; i < 4; ++i) {
        int kl = kr + i * 8;
        int col = cblk + cl;
        const float* W = (col < G4) ? Wx_f : Wx_b;
        int c2 = (col < G4) ? col : col - G4;
        tile[kl][cl] = W[(size_t)(kblk + kl) * G4 + c2];
    }
    __syncthreads();
    int kl2 = tid & 31, cr = tid >> 5;
#pragma unroll
    for (int i = 0; i < 4; ++i) {
        int cl2 = cr + i * 8;
        float v = tile[kl2][cl2];
        __nv_bfloat16 hi = __float2bfloat16_rn(v);
        __nv_bfloat16 lo = __float2bfloat16_rn(v - __bfloat162float(hi));
        size_t o = (size_t)(cblk + cl2) * D_IN + kblk + kl2;
        g_whi[o] = hi;
        g_wlo[o] = lo;
    }
}

// ---------------- kernel 3: xg = A @ W^T via mma.sync bf16 3-split ----------------
// Block 128x128, 8 warps (4m x 2n), warp tile 32x64. K staged 64/iter, 16 stages,
// cp.async double buffer, SW128 smem. Splits: Ahi*Whi + Ahi*Wlo + Alo*Whi.
// smem: [buf][4 tiles of 16KB: Ahi, Alo, Whi, Wlo] = 131072 B.
#define GSM_TOT 131072

__global__ void __launch_bounds__(256, 1)
mma_gemm_kernel() {
    extern __shared__ char smg[];
    const int tid = threadIdx.x, lane = tid & 31, wid = tid >> 5;
    const int cb = blockIdx.x, rb = blockIdx.y;
    const unsigned sbase = smem_u32(smg);
    const int warp_m = wid >> 1, warp_n = wid & 1;

    const __nv_bfloat16* src0 = g_ahi + (size_t)rb * 128 * D_IN;
    const __nv_bfloat16* src1 = g_alo + (size_t)rb * 128 * D_IN;
    const __nv_bfloat16* src2 = g_whi + (size_t)cb * 128 * D_IN;
    const __nv_bfloat16* src3 = g_wlo + (size_t)cb * 128 * D_IN;

    auto load_stage = [&](int kt, int buf) {
        unsigned dbase = sbase + buf * 65536;
#pragma unroll
        for (int i = 0; i < 16; ++i) {
            int c = tid + i * 256;             // 4096 16B-chunks
            int m = c >> 10, cc = c & 1023;
            int row = cc >> 3, kc = cc & 7;
            const __nv_bfloat16* s =
                (m == 0 ? src0 : m == 1 ? src1 : m == 2 ? src2 : src3)
                + (size_t)row * D_IN + kt * 64 + kc * 8;
            unsigned off = (unsigned)(row * 128 + kc * 16);
            cp16(dbase + m * 16384 + SWZ(off), s);
        }
    };

    float acc[2][8][4];
#pragma unroll
    for (int mt = 0; mt < 2; ++mt)
#pragma unroll
        for (int nt = 0; nt < 8; ++nt)
#pragma unroll
            for (int r = 0; r < 4; ++r) acc[mt][nt][r] = 0.0f;

    // lane offsets for ldmatrix addressing
    const unsigned la_row = lane & 15;           // A: row within m16 tile
    const unsigned la_kh  = lane >> 4;           // A: k half (0/1)
    const unsigned lb_row = (lane & 7) + ((lane >> 4) << 3);  // B: row within n16 pair
    const unsigned lb_kh  = (lane >> 3) & 1;     // B: k half

    load_stage(0, 0); cp_commit();

    for (int ti = 0; ti < 16; ++ti) {
        const int buf = ti & 1;
        if (ti + 1 < 16) {
            load_stage(ti + 1, buf ^ 1); cp_commit();
            cp_wait<1>();
        } else {
            cp_wait<0>();
        }
        __syncthreads();

        const unsigned base = sbase + buf * 65536;
#pragma unroll
        for (int sp = 0; sp < 3; ++sp) {
            const unsigned abase = base + (sp == 2 ? 16384 : 0);
            const unsigned wbase = base + (sp == 1 ? 49152 : 32768);
#pragma unroll
            for (int k16 = 0; k16 < 4; ++k16) {
                unsigned a[2][4];
#pragma unroll
                for (int mt = 0; mt < 2; ++mt) {
                    unsigned off = (unsigned)((warp_m * 32 + mt * 16 + la_row) * 128
                                              + k16 * 32 + la_kh * 16);
                    ldsm_x4(a[mt][0], a[mt][1], a[mt][2], a[mt][3], abase + SWZ(off));
                }
#pragma unroll
                for (int np = 0; np < 4; ++np) {     // pair of n8 tiles
                    unsigned b0, b1, b2, b3;
                    unsigned off = (unsigned)((warp_n * 64 + np * 16 + lb_row) * 128
                                              + k16 * 32 + lb_kh * 16);
                    ldsm_x4(b0, b1, b2, b3, wbase + SWZ(off));
#pragma unroll
                    for (int mt = 0; mt < 2; ++mt) {
                        mma_bf16(acc[mt][np * 2],     a[mt][0], a[mt][1], a[mt][2], a[mt][3], b0, b1);
                        mma_bf16(acc[mt][np * 2 + 1], a[mt][0], a[mt][1], a[mt][2], a[mt][3], b2, b3);
                    }
                }
            }
        }
        __syncthreads();
    }

    // epilogue: col-major store g_xg[col][row]
    const int r0 = rb * 128 + warp_m * 32 + (lane >> 2);
#pragma unroll
    for (int mt = 0; mt < 2; ++mt)
#pragma unroll
        for (int nt = 0; nt < 8; ++nt) {
            size_t col = (size_t)cb * 128 + warp_n * 64 + nt * 8 + 2 * (lane & 3);
            int row = r0 + mt * 16;
            g_xg[col * ROWS + row]           = acc[mt][nt][0];
            g_xg[(col + 1) * ROWS + row]     = acc[mt][nt][1];
            g_xg[col * ROWS + row + 8]       = acc[mt][nt][2];
            g_xg[(col + 1) * ROWS + row + 8] = acc[mt][nt][3];
        }
}

// ---------------- kernel 4: persistent recurrent phase (R8, proven) ----------------
__global__ void __launch_bounds__(256, 1)
lstm_kernel(const float* __restrict__ Wh_f, const float* __restrict__ Wh_b,
            const float* __restrict__ b_f,  const float* __restrict__ b_b,
            const float* __restrict__ Wfc)
{
    extern __shared__ float sm[];
    float* hs   = sm;             // 16384 fl (64KB) : h(t-1) [k][b]
    float* ws   = sm + 16384;     // 16384 fl (64KB) : Wh slice [k][cc]
    float* part = sm + 32768;     // 16384 fl (64KB) : [slice][cc][b]
    float* psum = sm + 49152;     // 256 fl
    unsigned long long* mbar_p = (unsigned long long*)(sm + 49408);

    const int tid = threadIdx.x;
    const int blk = blockIdx.x;
    const int dir = blk >> 6;
    const int j0  = (blk & 63) * 8;
    const bool checker = ((blk & 63) == 0);

    const int slice = tid >> 4;          // 0..15 (k range slice*32..+31)
    const int q     = tid & 15;
    const int bo    = q >> 2;            // batch octet
    const int cq    = q & 3;             // col octet

    const int u = tid >> 5;              // hidden unit 0..7
    const int b = tid & 31;              // batch

    const float* Wh   = dir ? Wh_b : Wh_f;
    const float* bias = dir ? b_b  : b_f;

    const unsigned mbar = smem_u32(mbar_p);
    const unsigned hs_u = smem_u32(hs);
    if (tid == 0) mbar_init(mbar, 1);

    for (int e = tid; e < 512 * 32; e += 256) {
        int k = e >> 5, cc = e & 31;
        ws[e] = Wh[(size_t)k * G4 + (cc >> 3) * 512 + j0 + (cc & 7)];
    }

    float biasr[4];
#pragma unroll
    for (int g = 0; g < 4; ++g) biasr[g] = bias[g * 512 + j0 + u];
    const float wfc = Wfc[dir * H_HID + j0 + u];

    float cstate = 0.0f;
    __syncthreads();

    for (int s = 0; s < T_LEN; ++s) {
        const int t = dir ? (T_LEN - 1 - s) : s;
        const float* hprev = g_hbuf[s & 1][dir];
        float*       hnext = g_hbuf[(s + 1) & 1][dir];

        float xgv[4];
#pragma unroll
        for (int g = 0; g < 4; ++g)
            xgv[g] = __ldg(g_xg + (size_t)(dir * G4 + g * 512 + j0 + u) * ROWS + t * 32 + b);

        if (s > 0) {
            if (checker) {
                if (tid < 32) {
                    const unsigned* fa = &g_flag[dir][tid];
                    const unsigned* fb = &g_flag[dir][tid + 32];
                    bool ok;
                    do {
                        ok = (ld_acq(fa) >= (unsigned)s) && (ld_acq(fb) >= (unsigned)s);
                    } while (!__all_sync(0xffffffffu, ok));
                    if (tid == 0) st_rel(&g_gen2[dir], (unsigned)s);
                }
            } else {
                if (tid == 0) {
                    while (ld_acq(&g_gen2[dir]) < (unsigned)s) { }
                }
            }
        }
        if (tid == 0) {
            mbar_expect_tx(mbar, 65536u);
            bulk_g2s(hs_u, hprev, 65536u, mbar);
        }
        mbar_wait(mbar, s & 1);

        unsigned long long acc[8][4];
#pragma unroll
        for (int bi = 0; bi < 8; ++bi)
#pragma unroll
            for (int cp = 0; cp < 4; ++cp) acc[bi][cp] = 0ull;
        {
            const float* hp = hs + slice * 32 * 32 + bo * 8;
            const float* wp = ws + slice * 32 * 32 + cq * 8;
#pragma unroll 2
            for (int kk = 0; kk < 32; ++kk) {
                float4 h0 = *(const float4*)hp;
                float4 h1 = *(const float4*)(hp + 4);
                ulonglong2 wq0 = *(const ulonglong2*)wp;
                ulonglong2 wq1 = *(const ulonglong2*)(wp + 4);
                unsigned long long s0 = splat2(h0.x), s1 = splat2(h0.y);
                unsigned long long s2 = splat2(h0.z), s3 = splat2(h0.w);
                unsigned long long s4 = splat2(h1.x), s5 = splat2(h1.y);
                unsigned long long s6 = splat2(h1.z), s7 = splat2(h1.w);
                FMA2(acc[0][0], s0, wq0.x); FMA2(acc[0][1], s0, wq0.y);
                FMA2(acc[0][2], s0, wq1.x); FMA2(acc[0][3], s0, wq1.y);
                FMA2(acc[1][0], s1, wq0.x); FMA2(acc[1][1], s1, wq0.y);
                FMA2(acc[1][2], s1, wq1.x); FMA2(acc[1][3], s1, wq1.y);
                FMA2(acc[2][0], s2, wq0.x); FMA2(acc[2][1], s2, wq0.y);
                FMA2(acc[2][2], s2, wq1.x); FMA2(acc[2][3], s2, wq1.y);
                FMA2(acc[3][0], s3, wq0.x); FMA2(acc[3][1], s3, wq0.y);
                FMA2(acc[3][2], s3, wq1.x); FMA2(acc[3][3], s3, wq1.y);
                FMA2(acc[4][0], s4, wq0.x); FMA2(acc[4][1], s4, wq0.y);
                FMA2(acc[4][2], s4, wq1.x); FMA2(acc[4][3], s4, wq1.y);
                FMA2(acc[5][0], s5, wq0.x); FMA2(acc[5][1], s5, wq0.y);
                FMA2(acc[5][2], s5, wq1.x); FMA2(acc[5][3], s5, wq1.y);
                FMA2(acc[6][0], s6, wq0.x); FMA2(acc[6][1], s6, wq0.y);
                FMA2(acc[6][2], s6, wq1.x); FMA2(acc[6][3], s6, wq1.y);
                FMA2(acc[7][0], s7, wq0.x); FMA2(acc[7][1], s7, wq0.y);
                FMA2(acc[7][2], s7, wq1.x); FMA2(acc[7][3], s7, wq1.y);
                hp += 32; wp += 32;
            }
        }
        {
            float* pb = part + slice * 1024 + bo * 8;
#pragma unroll
            for (int cp = 0; cp < 4; ++cp) {
                float* p0 = pb + (cq * 8 + 2 * cp) * 32;
#pragma unroll
                for (int bi = 0; bi < 8; ++bi) {
                    float lo, hi;
                    unpack2(acc[bi][cp], lo, hi);
                    p0[bi]      = lo;
                    p0[32 + bi] = hi;
                }
            }
        }
        __syncthreads();

        {
            float gate[4];
#pragma unroll
            for (int g = 0; g < 4; ++g) {
                float sum = xgv[g] + biasr[g];
                const float* pp = part + (g * 8 + u) * 32 + b;
#pragma unroll
                for (int sl = 0; sl < 16; ++sl) sum += pp[sl * 1024];
                gate[g] = sum;
            }
            float iv = 1.0f / (1.0f + __expf(-gate[0]));
            float fv = 1.0f / (1.0f + __expf(-gate[1]));
            float gv = tanhf(gate[2]);
            float ov = 1.0f / (1.0f + __expf(-gate[3]));
            cstate = fv * cstate + iv * gv;
            float hv = ov * tanhf(cstate);
            hnext[(j0 + u) * 32 + b] = hv;
            psum[tid] = hv * wfc;
        }
        __syncthreads();
        if (tid == 64 && s + 1 < T_LEN)
            st_rel(&g_flag[dir][blk & 63], (unsigned)(s + 1));
        if (tid < 32) {
            float tot = 0.0f;
#pragma unroll
            for (int uu = 0; uu < 8; ++uu) tot += psum[tid + uu * 32];
            g_part[blk][t][tid] = tot;
        }
    }
}

// ---------------- kernel 5: reduce partials + sigmoid ----------------
__global__ void finalize_kernel(const float* __restrict__ b_fc, float* __restrict__ out) {
    int g = blockIdx.x * blockDim.x + threadIdx.x;
    if (g >= T_LEN * BATCH) return;
    int t = g >> 5, b = g & 31;
    float acc = b_fc[0];
    const float* p = &g_part[0][t][b];
#pragma unroll 8
    for (int blk = 0; blk < 128; ++blk)
        acc += p[(size_t)blk * T_LEN * BATCH];
    out[(size_t)b * T_LEN + t] = 1.0f / (1.0f + __expf(-acc));
}

// ---------------- launcher ----------------
extern "C" void kernel_launch(void* const* d_in, const int* in_sizes, int n_in,
                              void* d_out, int out_size) {
    const float* x    = (const float*)d_in[0];
    const float* Wx_f = (const float*)d_in[1];
    const float* Wh_f = (const float*)d_in[2];
    const float* b_f  = (const float*)d_in[3];
    const float* Wx_b = (const float*)d_in[4];
    const float* Wh_b = (const float*)d_in[5];
    const float* b_b  = (const float*)d_in[6];
    const float* Wfc  = (const float*)d_in[7];
    const float* bfc  = (const float*)d_in[8];
    float* out = (float*)d_out;
    (void)in_sizes; (void)n_in; (void)out_size;

    cudaFuncSetAttribute(mma_gemm_kernel, cudaFuncAttributeMaxDynamicSharedMemorySize, GSM_TOT);
    cudaFuncSetAttribute(lstm_kernel, cudaFuncAttributeMaxDynamicSharedMemorySize, 197664);

    zero_state_kernel<<<256, 256>>>();
    conv_x_kernel<<<ROWS * D_IN / 8 / 256, 256>>>(x);
    conv_w_kernel<<<dim3(NCOL / 32, D_IN / 32), 256>>>(Wx_f, Wx_b);
    mma_gemm_kernel<<<dim3(32, 256), 256, GSM_TOT>>>();
    lstm_kernel<<<128, 256, 197664>>>(Wh_f, Wh_b, b_f, b_b, Wfc);
    finalize_kernel<<<128, 256>>>(bfc, out);
}

// round 13
// speedup vs baseline: 2.7971x; 1.1943x over previous
#include <cuda_runtime.h>
#include <cuda_bf16.h>

#define T_LEN 1024
#define D_IN  1024
#define H_HID 512
#define G4    2048
#define BATCH 32
#define ROWS  32768          // T*B
#define NCOL  4096           // 2 dirs * 4H

// ---------------- device scratch ----------------
__device__ __align__(256) __nv_bfloat16 g_ahi[(size_t)ROWS * D_IN];  // A hi [row][k]
__device__ __align__(256) __nv_bfloat16 g_alo[(size_t)ROWS * D_IN];  // A lo
__device__ __align__(256) __nv_bfloat16 g_whi[(size_t)NCOL * D_IN];  // W^T hi [col][k]
__device__ __align__(256) __nv_bfloat16 g_wlo[(size_t)NCOL * D_IN];  // W^T lo
__device__ __align__(256) float g_xg[(size_t)NCOL * ROWS];   // input proj, col-major [col][row]
// recurrent h as bf16 hi/lo in SW128 tiled layout [kt=8][b=32][64 k] per dir/buf
__device__ __align__(256) char g_hA[2][2][32768];            // [buf][dir] hi
__device__ __align__(256) char g_hB[2][2][32768];            // [buf][dir] lo
__device__ __align__(256) float g_part[128][T_LEN][BATCH];   // per-block logit partials
__device__ __align__(256) unsigned g_flag[2][64];            // per-block completed-step counters
__device__ unsigned g_gen2[2];                               // per-dir published generation

// ---------------- acquire/release + mbarrier + bulk-copy helpers ----------------
__device__ __forceinline__ unsigned ld_acq(const unsigned* p) {
    unsigned v;
    asm volatile("ld.global.acquire.gpu.u32 %0, [%1];" : "=r"(v) : "l"(p) : "memory");
    return v;
}
__device__ __forceinline__ void st_rel(unsigned* p, unsigned v) {
    asm volatile("st.global.release.gpu.u32 [%0], %1;" :: "l"(p), "r"(v) : "memory");
}
__device__ __forceinline__ unsigned smem_u32(const void* p) {
    unsigned a;
    asm("{ .reg .u64 t; cvta.to.shared.u64 t, %1; cvt.u32.u64 %0, t; }" : "=r"(a) : "l"(p));
    return a;
}
__device__ __forceinline__ void mbar_init(unsigned mbar, unsigned count) {
    asm volatile("mbarrier.init.shared.b64 [%0], %1;" :: "r"(mbar), "r"(count) : "memory");
}
__device__ __forceinline__ void mbar_expect_tx(unsigned mbar, unsigned bytes) {
    asm volatile("mbarrier.arrive.expect_tx.shared.b64 _, [%0], %1;"
                 :: "r"(mbar), "r"(bytes) : "memory");
}
__device__ __forceinline__ void bulk_g2s(unsigned dst_smem, const void* src, unsigned bytes,
                                         unsigned mbar) {
    asm volatile(
        "cp.async.bulk.shared::cta.global.mbarrier::complete_tx::bytes [%0], [%1], %2, [%3];"
        :: "r"(dst_smem), "l"(src), "r"(bytes), "r"(mbar) : "memory");
}
__device__ __forceinline__ void mbar_wait(unsigned mbar, unsigned parity) {
    asm volatile(
        "{\n\t.reg .pred P;\n"
        "W%=:\n\t"
        "mbarrier.try_wait.parity.acquire.cta.shared::cta.b64 P, [%0], %1, 0x989680;\n\t"
        "@P bra D%=;\n\t"
        "bra W%=;\n"
        "D%=:\n\t}"
        :: "r"(mbar), "r"(parity) : "memory");
}

// ---------------- mma / ldmatrix / cp.async helpers (sm_80-era, sm_103-safe) ----------
__device__ __forceinline__ void ldsm_x4(unsigned& r0, unsigned& r1, unsigned& r2, unsigned& r3,
                                        unsigned addr) {
    asm volatile("ldmatrix.sync.aligned.m8n8.x4.shared.b16 {%0,%1,%2,%3}, [%4];"
                 : "=r"(r0), "=r"(r1), "=r"(r2), "=r"(r3) : "r"(addr));
}
__device__ __forceinline__ void mma_bf16(float* d, unsigned a0, unsigned a1, unsigned a2,
                                         unsigned a3, unsigned b0, unsigned b1) {
    asm volatile(
        "mma.sync.aligned.m16n8k16.row.col.f32.bf16.bf16.f32 "
        "{%0,%1,%2,%3}, {%4,%5,%6,%7}, {%8,%9}, {%0,%1,%2,%3};"
        : "+f"(d[0]), "+f"(d[1]), "+f"(d[2]), "+f"(d[3])
        : "r"(a0), "r"(a1), "r"(a2), "r"(a3), "r"(b0), "r"(b1));
}
__device__ __forceinline__ void cp16(unsigned dst, const void* src) {
    asm volatile("cp.async.cg.shared.global [%0], [%1], 16;" :: "r"(dst), "l"(src));
}
__device__ __forceinline__ void cp_commit() { asm volatile("cp.async.commit_group;"); }
template <int N>
__device__ __forceinline__ void cp_wait() { asm volatile("cp.async.wait_group %0;" :: "n"(N)); }

#define SWZ(off) ((off) ^ (((off) >> 3) & 0x70))

// ---------------- kernel 1: zero recurrent state + flags ----------------
__global__ void zero_state_kernel() {
    int i = blockIdx.x * blockDim.x + threadIdx.x;       // 65536 threads
    if (i < 32768) ((unsigned*)g_hA)[i] = 0u;            // 131072 B = 32768 u32
    else           ((unsigned*)g_hB)[i - 32768] = 0u;
    if (i < 128) ((unsigned*)g_flag)[i] = 0u;
    if (i < 2)   g_gen2[i] = 0u;
}

// ---------------- kernel 2a: x -> bf16 hi/lo, row = t*32+b, k-major ----------------
__global__ void conv_x_kernel(const float* __restrict__ x) {
    int idx = blockIdx.x * blockDim.x + threadIdx.x;
    int row = idx >> 7;
    int kc  = (idx & 127) * 8;
    int b = row & 31, t = row >> 5;
    const float4* src = (const float4*)(x + ((size_t)b * T_LEN + t) * D_IN + kc);
    float4 v0 = src[0], v1 = src[1];
    float vs[8] = {v0.x, v0.y, v0.z, v0.w, v1.x, v1.y, v1.z, v1.w};
    __nv_bfloat16 hi[8], lo[8];
#pragma unroll
    for (int i = 0; i < 8; ++i) {
        hi[i] = __float2bfloat16_rn(vs[i]);
        lo[i] = __float2bfloat16_rn(vs[i] - __bfloat162float(hi[i]));
    }
    *(uint4*)(g_ahi + (size_t)row * D_IN + kc) = *(uint4*)hi;
    *(uint4*)(g_alo + (size_t)row * D_IN + kc) = *(uint4*)lo;
}

// ---------------- kernel 2b: W [k][col] -> W^T bf16 hi/lo [col][k] ----------------
__global__ void conv_w_kernel(const float* __restrict__ Wx_f, const float* __restrict__ Wx_b) {
    __shared__ float tile[32][33];
    int cblk = blockIdx.x * 32;
    int kblk = blockIdx.y * 32;
    int tid = threadIdx.x;
    int cl = tid & 31, kr = tid >> 5;
#pragma unroll
    for (int i = 0; i < 4; ++i) {
        int kl = kr + i * 8;
        int col = cblk + cl;
        const float* W = (col < G4) ? Wx_f : Wx_b;
        int c2 = (col < G4) ? col : col - G4;
        tile[kl][cl] = W[(size_t)(kblk + kl) * G4 + c2];
    }
    __syncthreads();
    int kl2 = tid & 31, cr = tid >> 5;
#pragma unroll
    for (int i = 0; i < 4; ++i) {
        int cl2 = cr + i * 8;
        float v = tile[kl2][cl2];
        __nv_bfloat16 hi = __float2bfloat16_rn(v);
        __nv_bfloat16 lo = __float2bfloat16_rn(v - __bfloat162float(hi));
        size_t o = (size_t)(cblk + cl2) * D_IN + kblk + kl2;
        g_whi[o] = hi;
        g_wlo[o] = lo;
    }
}

// ---------------- kernel 3: xg = A @ W^T via mma.sync bf16 3-split (proven R12) -------
#define GSM_TOT 131072

__global__ void __launch_bounds__(256, 1)
mma_gemm_kernel() {
    extern __shared__ char smg[];
    const int tid = threadIdx.x, lane = tid & 31, wid = tid >> 5;
    const int cb = blockIdx.x, rb = blockIdx.y;
    const unsigned sbase = smem_u32(smg);
    const int warp_m = wid >> 1, warp_n = wid & 1;

    const __nv_bfloat16* src0 = g_ahi + (size_t)rb * 128 * D_IN;
    const __nv_bfloat16* src1 = g_alo + (size_t)rb * 128 * D_IN;
    const __nv_bfloat16* src2 = g_whi + (size_t)cb * 128 * D_IN;
    const __nv_bfloat16* src3 = g_wlo + (size_t)cb * 128 * D_IN;

    auto load_stage = [&](int kt, int buf) {
        unsigned dbase = sbase + buf * 65536;
#pragma unroll
        for (int i = 0; i < 16; ++i) {
            int c = tid + i * 256;
            int m = c >> 10, cc = c & 1023;
            int row = cc >> 3, kc = cc & 7;
            const __nv_bfloat16* s =
                (m == 0 ? src0 : m == 1 ? src1 : m == 2 ? src2 : src3)
                + (size_t)row * D_IN + kt * 64 + kc * 8;
            unsigned off = (unsigned)(row * 128 + kc * 16);
            cp16(dbase + m * 16384 + SWZ(off), s);
        }
    };

    float acc[2][8][4];
#pragma unroll
    for (int mt = 0; mt < 2; ++mt)
#pragma unroll
        for (int nt = 0; nt < 8; ++nt)
#pragma unroll
            for (int r = 0; r < 4; ++r) acc[mt][nt][r] = 0.0f;

    const unsigned la_row = lane & 15;
    const unsigned la_kh  = lane >> 4;
    const unsigned lb_row = (lane & 7) + ((lane >> 4) << 3);
    const unsigned lb_kh  = (lane >> 3) & 1;

    load_stage(0, 0); cp_commit();

    for (int ti = 0; ti < 16; ++ti) {
        const int buf = ti & 1;
        if (ti + 1 < 16) {
            load_stage(ti + 1, buf ^ 1); cp_commit();
            cp_wait<1>();
        } else {
            cp_wait<0>();
        }
        __syncthreads();

        const unsigned base = sbase + buf * 65536;
#pragma unroll
        for (int sp = 0; sp < 3; ++sp) {
            const unsigned abase = base + (sp == 2 ? 16384 : 0);
            const unsigned wbase = base + (sp == 1 ? 49152 : 32768);
#pragma unroll
            for (int k16 = 0; k16 < 4; ++k16) {
                unsigned a[2][4];
#pragma unroll
                for (int mt = 0; mt < 2; ++mt) {
                    unsigned off = (unsigned)((warp_m * 32 + mt * 16 + la_row) * 128
                                              + k16 * 32 + la_kh * 16);
                    ldsm_x4(a[mt][0], a[mt][1], a[mt][2], a[mt][3], abase + SWZ(off));
                }
#pragma unroll
                for (int np = 0; np < 4; ++np) {
                    unsigned b0, b1, b2, b3;
                    unsigned off = (unsigned)((warp_n * 64 + np * 16 + lb_row) * 128
                                              + k16 * 32 + lb_kh * 16);
                    ldsm_x4(b0, b1, b2, b3, wbase + SWZ(off));
#pragma unroll
                    for (int mt = 0; mt < 2; ++mt) {
                        mma_bf16(acc[mt][np * 2],     a[mt][0], a[mt][1], a[mt][2], a[mt][3], b0, b1);
                        mma_bf16(acc[mt][np * 2 + 1], a[mt][0], a[mt][1], a[mt][2], a[mt][3], b2, b3);
                    }
                }
            }
        }
        __syncthreads();
    }

    const int r0 = rb * 128 + warp_m * 32 + (lane >> 2);
#pragma unroll
    for (int mt = 0; mt < 2; ++mt)
#pragma unroll
        for (int nt = 0; nt < 8; ++nt) {
            size_t col = (size_t)cb * 128 + warp_n * 64 + nt * 8 + 2 * (lane & 3);
            int row = r0 + mt * 16;
            g_xg[col * ROWS + row]           = acc[mt][nt][0];
            g_xg[(col + 1) * ROWS + row]     = acc[mt][nt][1];
            g_xg[col * ROWS + row + 8]       = acc[mt][nt][2];
            g_xg[(col + 1) * ROWS + row + 8] = acc[mt][nt][3];
        }
}

// ---------------- kernel 4: persistent recurrent phase, tensor-core k-loop ----------
// 128 blocks, 256 threads. dir = blk>>6, 8 hidden units/block = 32 gate cols.
// Warp w owns k-slice [64w, 64w+64): 3-split bf16 mma (96 HMMA + 32 ldsm / warp / step).
// h stored in global as bf16 hi/lo, SW128 tiled [kt][b][64k]; staged via bulk copy.
// smem layout (bytes): A_hi 0..32K, A_lo 32K..64K, W_hi 64K..96K, W_lo 96K..128K,
//                      part 128K..160K, psum 160K..161K, mbar 161K+
#define LSM_PART 131072
#define LSM_PSUM 163840
#define LSM_MBAR 164864
#define LSM_TOT  164896

__global__ void __launch_bounds__(256, 1)
lstm_kernel(const float* __restrict__ Wh_f, const float* __restrict__ Wh_b,
            const float* __restrict__ b_f,  const float* __restrict__ b_b,
            const float* __restrict__ Wfc)
{
    extern __shared__ char smg[];
    float* part = (float*)(smg + LSM_PART);    // [w 8][cc 32][b 32]
    float* psum = (float*)(smg + LSM_PSUM);

    const int tid  = threadIdx.x;
    const int lane = tid & 31;
    const int w    = tid >> 5;                 // warp 0..7 = k-slice
    const int blk  = blockIdx.x;
    const int dir  = blk >> 6;
    const int j0   = (blk & 63) * 8;
    const bool checker = ((blk & 63) == 0);

    const int u = tid >> 5;                    // hidden unit 0..7
    const int b = tid & 31;                    // batch

    const float* Wh   = dir ? Wh_b : Wh_f;
    const float* bias = dir ? b_b  : b_f;

    const unsigned sbase = smem_u32(smg);
    const unsigned mbar  = smem_u32(smg + LSM_MBAR);
    if (tid == 0) mbar_init(mbar, 1);

    // convert Wh slice -> smem bf16 hi/lo, SW128 tiled [kt][cc][64k]
    for (int e = tid; e < 512 * 32; e += 256) {
        int k = e >> 5, cc = e & 31;
        float v = Wh[(size_t)k * G4 + (cc >> 3) * 512 + j0 + (cc & 7)];
        __nv_bfloat16 hi = __float2bfloat16_rn(v);
        __nv_bfloat16 lo = __float2bfloat16_rn(v - __bfloat162float(hi));
        int kt = k >> 6, kc = k & 63;
        unsigned byte = (unsigned)(kt * 4096 + cc * 128 + kc * 2);
        *(__nv_bfloat16*)(smg + 65536 + SWZ(byte)) = hi;
        *(__nv_bfloat16*)(smg + 98304 + SWZ(byte)) = lo;
    }

    float biasr[4];
#pragma unroll
    for (int g = 0; g < 4; ++g) biasr[g] = bias[g * 512 + j0 + u];
    const float wfc = Wfc[dir * H_HID + j0 + u];

    // ldmatrix lane offsets (same as proven GEMM)
    const unsigned la_row = lane & 15;
    const unsigned la_kh  = lane >> 4;
    const unsigned lb_row = (lane & 7) + ((lane >> 4) << 3);
    const unsigned lb_kh  = (lane >> 3) & 1;
    const unsigned kt_off = (unsigned)(w * 4096);

    // producer write address for this thread's h element (j = j0+u)
    const int jj = j0 + u;
    const unsigned h_byte = SWZ((unsigned)((jj >> 6) * 4096 + b * 128 + (jj & 63) * 2));

    float cstate = 0.0f;
    __syncthreads();

    for (int s = 0; s < T_LEN; ++s) {
        const int t = dir ? (T_LEN - 1 - s) : s;

        // prefetch xg (independent of h)
        float xgv[4];
#pragma unroll
        for (int g = 0; g < 4; ++g)
            xgv[g] = __ldg(g_xg + (size_t)(dir * G4 + g * 512 + j0 + u) * ROWS + t * 32 + b);

        // inter-block sync: flags -> checker -> gen (tid0-only polling)
        if (s > 0) {
            if (checker) {
                if (tid < 32) {
                    const unsigned* fa = &g_flag[dir][tid];
                    const unsigned* fb = &g_flag[dir][tid + 32];
                    bool ok;
                    do {
                        ok = (ld_acq(fa) >= (unsigned)s) && (ld_acq(fb) >= (unsigned)s);
                    } while (!__all_sync(0xffffffffu, ok));
                    if (tid == 0) st_rel(&g_gen2[dir], (unsigned)s);
                }
            } else {
                if (tid == 0) {
                    while (ld_acq(&g_gen2[dir]) < (unsigned)s) { }
                }
            }
        }
        // stage h(t-1) hi/lo: two 32KB bulk copies
        if (tid == 0) {
            mbar_expect_tx(mbar, 65536u);
            bulk_g2s(sbase,          g_hA[s & 1][dir], 32768u, mbar);
            bulk_g2s(sbase + 32768u, g_hB[s & 1][dir], 32768u, mbar);
        }
        mbar_wait(mbar, s & 1);

        // tensor k-phase: warp w covers kt=w (4 k16 tiles), 3 splits
        float acc[2][4][4];
#pragma unroll
        for (int mt = 0; mt < 2; ++mt)
#pragma unroll
            for (int nt = 0; nt < 4; ++nt)
#pragma unroll
                for (int r = 0; r < 4; ++r) acc[mt][nt][r] = 0.0f;

#pragma unroll
        for (int sp = 0; sp < 3; ++sp) {
            const unsigned abase = sbase + (sp == 2 ? 32768u : 0u);
            const unsigned wbase = sbase + 65536u + (sp == 1 ? 32768u : 0u);
#pragma unroll
            for (int k16 = 0; k16 < 4; ++k16) {
                unsigned a[2][4];
#pragma unroll
                for (int mt = 0; mt < 2; ++mt) {
                    unsigned off = kt_off + (mt * 16 + la_row) * 128 + k16 * 32 + la_kh * 16;
                    ldsm_x4(a[mt][0], a[mt][1], a[mt][2], a[mt][3], abase + SWZ(off));
                }
#pragma unroll
                for (int np = 0; np < 2; ++np) {
                    unsigned b0, b1, b2, b3;
                    unsigned off = kt_off + (np * 16 + lb_row) * 128 + k16 * 32 + lb_kh * 16;
                    ldsm_x4(b0, b1, b2, b3, wbase + SWZ(off));
#pragma unroll
                    for (int mt = 0; mt < 2; ++mt) {
                        mma_bf16(acc[mt][np * 2],     a[mt][0], a[mt][1], a[mt][2], a[mt][3], b0, b1);
                        mma_bf16(acc[mt][np * 2 + 1], a[mt][0], a[mt][1], a[mt][2], a[mt][3], b2, b3);
                    }
                }
            }
        }
        // write warp partials: part[w][cc][b]
        {
            const int brow = lane >> 2;
            const int c0 = (lane & 3) * 2;
#pragma unroll
            for (int mt = 0; mt < 2; ++mt)
#pragma unroll
                for (int nt = 0; nt < 4; ++nt) {
                    int cc = nt * 8 + c0;
                    int bb = mt * 16 + brow;
                    float* pp = part + w * 1024;
                    pp[cc * 32 + bb]            = acc[mt][nt][0];
                    pp[(cc + 1) * 32 + bb]      = acc[mt][nt][1];
                    pp[cc * 32 + bb + 8]        = acc[mt][nt][2];
                    pp[(cc + 1) * 32 + bb + 8]  = acc[mt][nt][3];
                }
        }
        __syncthreads();

        // epilogue: thread (u, b) computes cell update
        {
            float gate[4];
#pragma unroll
            for (int g = 0; g < 4; ++g) {
                float sum = xgv[g] + biasr[g];
                const float* pp = part + (g * 8 + u) * 32 + b;
#pragma unroll
                for (int sl = 0; sl < 8; ++sl) sum += pp[sl * 1024];
                gate[g] = sum;
            }
            float iv = 1.0f / (1.0f + __expf(-gate[0]));
            float fv = 1.0f / (1.0f + __expf(-gate[1]));
            float gv = tanhf(gate[2]);
            float ov = 1.0f / (1.0f + __expf(-gate[3]));
            cstate = fv * cstate + iv * gv;
            float hv = ov * tanhf(cstate);
            // publish h as bf16 hi/lo into swizzled tiled layout
            __nv_bfloat16 hhi = __float2bfloat16_rn(hv);
            __nv_bfloat16 hlo = __float2bfloat16_rn(hv - __bfloat162float(hhi));
            *(__nv_bfloat16*)(g_hA[(s + 1) & 1][dir] + h_byte) = hhi;
            *(__nv_bfloat16*)(g_hB[(s + 1) & 1][dir] + h_byte) = hlo;
            psum[tid] = hv * wfc;
        }
        __syncthreads();
        // publish step completion (h writes ordered by syncthreads before release)
        if (tid == 64 && s + 1 < T_LEN)
            st_rel(&g_flag[dir][blk & 63], (unsigned)(s + 1));
        if (tid < 32) {
            float tot = 0.0f;
#pragma unroll
            for (int uu = 0; uu < 8; ++uu) tot += psum[tid + uu * 32];
            g_part[blk][t][tid] = tot;
        }
    }
}

// ---------------- kernel 5: reduce partials + sigmoid ----------------
__global__ void finalize_kernel(const float* __restrict__ b_fc, float* __restrict__ out) {
    int g = blockIdx.x * blockDim.x + threadIdx.x;
    if (g >= T_LEN * BATCH) return;
    int t = g >> 5, b = g & 31;
    float acc = b_fc[0];
    const float* p = &g_part[0][t][b];
#pragma unroll 8
    for (int blk = 0; blk < 128; ++blk)
        acc += p[(size_t)blk * T_LEN * BATCH];
    out[(size_t)b * T_LEN + t] = 1.0f / (1.0f + __expf(-acc));
}

// ---------------- launcher ----------------
extern "C" void kernel_launch(void* const* d_in, const int* in_sizes, int n_in,
                              void* d_out, int out_size) {
    const float* x    = (const float*)d_in[0];
    const float* Wx_f = (const float*)d_in[1];
    const float* Wh_f = (const float*)d_in[2];
    const float* b_f  = (const float*)d_in[3];
    const float* Wx_b = (const float*)d_in[4];
    const float* Wh_b = (const float*)d_in[5];
    const float* b_b  = (const float*)d_in[6];
    const float* Wfc  = (const float*)d_in[7];
    const float* bfc  = (const float*)d_in[8];
    float* out = (float*)d_out;
    (void)in_sizes; (void)n_in; (void)out_size;

    cudaFuncSetAttribute(mma_gemm_kernel, cudaFuncAttributeMaxDynamicSharedMemorySize, GSM_TOT);
    cudaFuncSetAttribute(lstm_kernel, cudaFuncAttributeMaxDynamicSharedMemorySize, LSM_TOT);

    zero_state_kernel<<<256, 256>>>();
    conv_x_kernel<<<ROWS * D_IN / 8 / 256, 256>>>(x);
    conv_w_kernel<<<dim3(NCOL / 32, D_IN / 32), 256>>>(Wx_f, Wx_b);
    mma_gemm_kernel<<<dim3(32, 256), 256, GSM_TOT>>>();
    lstm_kernel<<<128, 256, LSM_TOT>>>(Wh_f, Wh_b, b_f, b_b, Wfc);
    finalize_kernel<<<128, 256>>>(bfc, out);
}